// round 2
// baseline (speedup 1.0000x reference)
#include <cuda_runtime.h>
#include <cstdint>

// ---------------------------------------------------------------------------
// GraphEncoder: batched dense 2-layer GCN on GB300 (sm_103a)
//   out = nrm @ relu(nrm @ (x W1) + b1) W2 ... with nrm = D^-1/2 (A+I) D^-1/2
// Fused form with ds[i] = rsqrt(1 + rowsum(A)[i]):
//   P'  = ds ∘ (X W)                (row-scaled feature product)
//   nrm @ (X W) = ds_i * ( (A @ P')_i + P'_i )
// ---------------------------------------------------------------------------

#define DEV_INLINE __device__ __forceinline__

static constexpr int BATCH = 8;
static constexpr int NNODE = 4096;
static constexpr int INC   = 256;
static constexpr int HIDC  = 512;
static constexpr int OUTC  = 256;

// Scratch (allocation-free: __device__ globals)
__device__ float g_ds[BATCH * NNODE];                          // 128 KB
__device__ float g_P1[(size_t)BATCH * NNODE * HIDC];           // 64 MB
__device__ float g_H [(size_t)BATCH * NNODE * HIDC];           // 64 MB
__device__ float g_P2[(size_t)BATCH * NNODE * OUTC];           // 32 MB

// ---------------------------------------------------------------------------
// PTX helpers
// ---------------------------------------------------------------------------
DEV_INLINE uint32_t cvt_tf32(float x) {
    uint32_t r;
    asm("cvt.rna.tf32.f32 %0, %1;" : "=r"(r) : "f"(x));
    return r;
}

DEV_INLINE void mma_m16n8k8_tf32(float* d,
                                 uint32_t a0, uint32_t a1, uint32_t a2, uint32_t a3,
                                 uint32_t b0, uint32_t b1) {
    asm volatile(
        "mma.sync.aligned.m16n8k8.row.col.f32.tf32.tf32.f32 "
        "{%0,%1,%2,%3},{%4,%5,%6,%7},{%8,%9},{%0,%1,%2,%3};"
        : "+f"(d[0]), "+f"(d[1]), "+f"(d[2]), "+f"(d[3])
        : "r"(a0), "r"(a1), "r"(a2), "r"(a3), "r"(b0), "r"(b1));
}

DEV_INLINE void cp_async16(uint32_t saddr, const void* gmem) {
    asm volatile("cp.async.cg.shared.global [%0], [%1], 16;" :: "r"(saddr), "l"(gmem));
}
DEV_INLINE void cp_commit() { asm volatile("cp.async.commit_group;"); }
template <int N> DEV_INLINE void cp_wait() { asm volatile("cp.async.wait_group %0;" :: "n"(N)); }

DEV_INLINE uint32_t smem_u32(const void* p) {
    return (uint32_t)__cvta_generic_to_shared(p);
}

// ---------------------------------------------------------------------------
// ds[row] = rsqrt(1 + sum_j A[row, j]),  one block (256 thr) per row
// ---------------------------------------------------------------------------
__global__ void __launch_bounds__(256) row_ds_kernel(const float* __restrict__ A,
                                                     float* __restrict__ ds) {
    long long row = blockIdx.x;
    const float4* p = (const float4*)(A + row * (long long)NNODE);
    float s = 0.f;
    #pragma unroll 4
    for (int i = threadIdx.x; i < NNODE / 4; i += 256) {
        float4 v = p[i];
        s += (v.x + v.y) + (v.z + v.w);
    }
    #pragma unroll
    for (int o = 16; o; o >>= 1) s += __shfl_xor_sync(0xFFFFFFFFu, s, o);
    __shared__ float ws[8];
    if ((threadIdx.x & 31) == 0) ws[threadIdx.x >> 5] = s;
    __syncthreads();
    if (threadIdx.x == 0) {
        float tot = 0.f;
        #pragma unroll
        for (int i = 0; i < 8; i++) tot += ws[i];
        ds[row] = rsqrtf(tot + 1.0f);
    }
}

// ---------------------------------------------------------------------------
// tf32 tensor-core GEMM, 128x128x32 block tile, 256 threads (8 warps, 2x4),
// warp tile 64x32 = 4x4 m16n8k8 tiles, double-buffered cp.async.
//
//  C = A(MxK, row-major fp32) @ B(KxN, row-major fp32)
//  GCN_EPI : C[i,n] = (relu?)( ds[i] * (acc + B[i,n]) + bias[n] )   (needs M==K)
//  else    : C[i,n] = SCALE_ROWS ? ds[i]*acc : acc
// ---------------------------------------------------------------------------
template <bool GCN_EPI, bool RELU, bool SCALE_ROWS>
__global__ void __launch_bounds__(256) gemm_tf32_kernel(
    const float* __restrict__ Ag, const float* __restrict__ Bg, float* __restrict__ Cg,
    const float* __restrict__ ds, const float* __restrict__ bias,
    int M, int N, int K,
    long long strideAb, long long strideBb, long long strideCb, int dsStride) {

    constexpr int BM = 128, BN = 128, BK = 32;
    constexpr int SA_STRIDE = BK + 4;   // 36: conflict-free A frag loads
    constexpr int SB_STRIDE = BN + 8;   // 136: conflict-free B frag loads
    constexpr int SA_ELEMS = BM * SA_STRIDE;   // 4608
    constexpr int SB_ELEMS = BK * SB_STRIDE;   // 4352

    extern __shared__ float smem[];
    // layout: sA[2] then sB[2]

    const int b = blockIdx.z;
    const float* Ab = Ag + (long long)b * strideAb;
    const float* Bb = Bg + (long long)b * strideBb;
    float*       Cb = Cg + (long long)b * strideCb;
    const float* dsb = ds + (long long)b * dsStride;

    const int m0 = blockIdx.y * BM;
    const int n0 = blockIdx.x * BN;
    const int tid = threadIdx.x;

    auto loadA = [&](int stage, int kt) {
        float* s = smem + stage * SA_ELEMS;
        #pragma unroll
        for (int i = 0; i < 4; i++) {
            int q = tid + i * 256;          // 0..1023 float4s
            int row = q >> 3;               // 128 rows
            int c4  = (q & 7) << 2;         // 0,4,...,28
            const float* g = Ab + (long long)(m0 + row) * K + kt + c4;
            cp_async16(smem_u32(s + row * SA_STRIDE + c4), g);
        }
    };
    auto loadB = [&](int stage, int kt) {
        float* s = smem + 2 * SA_ELEMS + stage * SB_ELEMS;
        #pragma unroll
        for (int i = 0; i < 4; i++) {
            int q = tid + i * 256;
            int row = q >> 5;               // 32 rows
            int c4  = (q & 31) << 2;        // 0..124
            const float* g = Bb + (long long)(kt + row) * N + n0 + c4;
            cp_async16(smem_u32(s + row * SB_STRIDE + c4), g);
        }
    };

    const int warp = tid >> 5, lane = tid & 31;
    const int wm = warp >> 2, wn = warp & 3;       // 2 x 4 warp grid
    const int mW = wm * 64, nW = wn * 32;
    const int gr = lane >> 2, t = lane & 3;

    float acc[4][4][4];
    #pragma unroll
    for (int mi = 0; mi < 4; mi++)
        #pragma unroll
        for (int ni = 0; ni < 4; ni++)
            #pragma unroll
            for (int e = 0; e < 4; e++) acc[mi][ni][e] = 0.f;

    loadA(0, 0); loadB(0, 0); cp_commit();

    const int nK = K / BK;
    int stage = 0;
    for (int kt = 0; kt < nK; kt++) {
        if (kt + 1 < nK) {
            loadA(stage ^ 1, (kt + 1) * BK);
            loadB(stage ^ 1, (kt + 1) * BK);
            cp_commit();
            cp_wait<1>();
        } else {
            cp_wait<0>();
        }
        __syncthreads();

        const float* sA = smem + stage * SA_ELEMS;
        const float* sB = smem + 2 * SA_ELEMS + stage * SB_ELEMS;

        #pragma unroll
        for (int kk = 0; kk < BK; kk += 8) {
            uint32_t afr[4][4], bfr[4][2];
            #pragma unroll
            for (int mi = 0; mi < 4; mi++) {
                int r = mW + mi * 16;
                afr[mi][0] = cvt_tf32(sA[(r + gr)     * SA_STRIDE + kk + t]);
                afr[mi][1] = cvt_tf32(sA[(r + gr + 8) * SA_STRIDE + kk + t]);
                afr[mi][2] = cvt_tf32(sA[(r + gr)     * SA_STRIDE + kk + t + 4]);
                afr[mi][3] = cvt_tf32(sA[(r + gr + 8) * SA_STRIDE + kk + t + 4]);
            }
            #pragma unroll
            for (int ni = 0; ni < 4; ni++) {
                int c = nW + ni * 8 + gr;
                bfr[ni][0] = cvt_tf32(sB[(kk + t)     * SB_STRIDE + c]);
                bfr[ni][1] = cvt_tf32(sB[(kk + t + 4) * SB_STRIDE + c]);
            }
            #pragma unroll
            for (int mi = 0; mi < 4; mi++)
                #pragma unroll
                for (int ni = 0; ni < 4; ni++)
                    mma_m16n8k8_tf32(acc[mi][ni],
                                     afr[mi][0], afr[mi][1], afr[mi][2], afr[mi][3],
                                     bfr[ni][0], bfr[ni][1]);
        }
        __syncthreads();
        stage ^= 1;
    }

    // epilogue
    #pragma unroll
    for (int mi = 0; mi < 4; mi++) {
        #pragma unroll
        for (int ni = 0; ni < 4; ni++) {
            int row0 = m0 + mW + mi * 16 + gr;
            int col  = n0 + nW + ni * 8 + t * 2;
            #pragma unroll
            for (int rr = 0; rr < 2; rr++) {
                int row = row0 + rr * 8;
                float v0 = acc[mi][ni][rr * 2 + 0];
                float v1 = acc[mi][ni][rr * 2 + 1];
                if (GCN_EPI) {
                    float d = dsb[row];
                    float2 sv = *(const float2*)(Bb + (long long)row * N + col);
                    v0 = fmaf(d, v0 + sv.x, bias[col]);
                    v1 = fmaf(d, v1 + sv.y, bias[col + 1]);
                    if (RELU) { v0 = fmaxf(v0, 0.f); v1 = fmaxf(v1, 0.f); }
                } else if (SCALE_ROWS) {
                    float d = dsb[row];
                    v0 *= d; v1 *= d;
                }
                *(float2*)(Cb + (long long)row * N + col) = make_float2(v0, v1);
            }
        }
    }
}

// ---------------------------------------------------------------------------
// launch
// ---------------------------------------------------------------------------
extern "C" void kernel_launch(void* const* d_in, const int* in_sizes, int n_in,
                              void* d_out, int out_size) {
    const float* x  = (const float*)d_in[0];   // [8,4096,256]
    const float* A  = (const float*)d_in[1];   // [8,4096,4096]
    const float* W1 = (const float*)d_in[2];   // [256,512]
    const float* b1 = (const float*)d_in[3];   // [512]
    const float* W2 = (const float*)d_in[4];   // [512,256]
    const float* b2 = (const float*)d_in[5];   // [256]
    float* out = (float*)d_out;                // [8,4096,256]

    float *ds, *P1, *H, *P2;
    cudaGetSymbolAddress((void**)&ds, g_ds);
    cudaGetSymbolAddress((void**)&P1, g_P1);
    cudaGetSymbolAddress((void**)&H,  g_H);
    cudaGetSymbolAddress((void**)&P2, g_P2);

    constexpr int SMEM_BYTES = (2 * 128 * 36 + 2 * 32 * 136) * 4;  // 71680

    cudaFuncSetAttribute(gemm_tf32_kernel<false, false, true>,
                         cudaFuncAttributeMaxDynamicSharedMemorySize, SMEM_BYTES);
    cudaFuncSetAttribute(gemm_tf32_kernel<true, true, false>,
                         cudaFuncAttributeMaxDynamicSharedMemorySize, SMEM_BYTES);
    cudaFuncSetAttribute(gemm_tf32_kernel<true, false, false>,
                         cudaFuncAttributeMaxDynamicSharedMemorySize, SMEM_BYTES);

    // 1) degree scales
    row_ds_kernel<<<BATCH * NNODE, 256>>>(A, ds);

    // 2) P1' = ds ∘ (x @ W1)   [32768,256]@[256,512]
    gemm_tf32_kernel<false, false, true>
        <<<dim3(HIDC / 128, (BATCH * NNODE) / 128, 1), 256, SMEM_BYTES>>>(
            x, W1, P1, ds, nullptr,
            BATCH * NNODE, HIDC, INC, 0, 0, 0, 0);

    // 3) H = relu( ds ∘ (A @ P1' + P1') + b1 )   per batch 4096x4096 @ 4096x512
    gemm_tf32_kernel<true, true, false>
        <<<dim3(HIDC / 128, NNODE / 128, BATCH), 256, SMEM_BYTES>>>(
            A, P1, H, ds, b1,
            NNODE, HIDC, NNODE,
            (long long)NNODE * NNODE, (long long)NNODE * HIDC,
            (long long)NNODE * HIDC, NNODE);

    // 4) P2' = ds ∘ (H @ W2)   [32768,512]@[512,256]
    gemm_tf32_kernel<false, false, true>
        <<<dim3(OUTC / 128, (BATCH * NNODE) / 128, 1), 256, SMEM_BYTES>>>(
            H, W2, P2, ds, nullptr,
            BATCH * NNODE, OUTC, HIDC, 0, 0, 0, 0);

    // 5) out = ds ∘ (A @ P2' + P2') + b2
    gemm_tf32_kernel<true, false, false>
        <<<dim3(OUTC / 128, NNODE / 128, BATCH), 256, SMEM_BYTES>>>(
            A, P2, out, ds, b2,
            NNODE, OUTC, NNODE,
            (long long)NNODE * NNODE, (long long)NNODE * OUTC,
            (long long)NNODE * OUTC, NNODE);
}